// round 12
// baseline (speedup 1.0000x reference)
#include <cuda_runtime.h>
#include <cuda_bf16.h>
#include <cstdint>

// DySample fused single-kernel: x(8,256,64,64), W_off(32,256), b_off(32)
//   -> out(8,256,128,128), fp32.
// Block = (h, b), 512 threads:
//   Phase 1: stage x[b,:,h,:] (64KB) + packed W (32KB) into smem.
//   Phase 2: offset GEMM with f32x2 accs, shfl.bfly reduction over cq lanes,
//            coords -> sxy smem (overlays dead W region). No gmem scratch.
//   Phase 3: 3x3-neighborhood bilinear gather (row h from smem, rows h+-1 via
//            __ldg / L2), packed-separable weights, float2 stores.
// ix = w + (0.25*off_x + ipx), iy = h + (0.25*off_y + ipy);
// j = g*4 + ry*2 + rx; o_x = j, o_y = 16 + j; ipx=(j&1)?+.25:-.25, ipy=((j>>1)&1)?+.25:-.25

#define Bn 8
#define Cn 256
#define Hn 64
#define Wn 64
#define Gn 4
#define NPOS 4096
#define OH 128
#define OW 128

#define SMEM_XS    0            // float xs[256][64]  = 65536 B
#define SMEM_WP    65536        // ull  Wp[16][256]   = 32768 B (GEMM) / sxy overlay
#define SMEM_TOTAL (65536 + 32768)

typedef unsigned long long ull;

__device__ __forceinline__ void ffma2(ull &d, ull a, ull b) {
    asm("fma.rn.f32x2 %0, %1, %2, %0;" : "+l"(d) : "l"(a), "l"(b));
}
__device__ __forceinline__ ull mul2(ull a, ull b) {
    ull r;
    asm("mul.rn.f32x2 %0, %1, %2;" : "=l"(r) : "l"(a), "l"(b));
    return r;
}
__device__ __forceinline__ ull add2(ull a, ull b) {
    ull r;
    asm("add.rn.f32x2 %0, %1, %2;" : "=l"(r) : "l"(a), "l"(b));
    return r;
}
__device__ __forceinline__ ull pack2(float lo, float hi) {
    ull r;
    asm("mov.b64 %0, {%1, %2};" : "=l"(r) : "f"(lo), "f"(hi));
    return r;
}
__device__ __forceinline__ void unpack2(ull v, float &lo, float &hi) {
    asm("mov.b64 {%0, %1}, %2;" : "=f"(lo), "=f"(hi) : "l"(v));
}

__global__ __launch_bounds__(512, 2) void dysample_fused(
    const float* __restrict__ x,
    const float* __restrict__ Woff,
    const float* __restrict__ boff,
    float* __restrict__ out)
{
    extern __shared__ __align__(16) char dsm[];
    float (*xs)[64]  = reinterpret_cast<float(*)[64]>(dsm + SMEM_XS);   // [256][64]
    ull   (*Wp)[256] = reinterpret_cast<ull(*)[256]>(dsm + SMEM_WP);    // [16][256]
    float (*sxy)[16][64] = reinterpret_cast<float(*)[16][64]>(dsm + SMEM_WP); // [2][16][64]

    const int tid = threadIdx.x;
    const int h   = blockIdx.x;
    const int b   = blockIdx.y;

    // ---- Phase 1: stage x row-slab + packed W ----
    {
        const float4* xg = (const float4*)(x + ((size_t)b * Cn * Hn + h) * Wn);
        // x[b][c][h][w]: row c starts at c*Hn*Wn + h*Wn; 16 float4 per row
        #pragma unroll
        for (int i = 0; i < 8; i++) {
            const int lin = i * 512 + tid;        // 0..4095
            const int c  = lin >> 4;
            const int w4 = lin & 15;
            const float4 v = __ldg((const float4*)(x
                + (((size_t)b * Cn + c) * Hn + h) * Wn) + w4);
            *(float4*)&xs[c][w4 * 4] = v;
        }
        (void)xg;
        #pragma unroll
        for (int i = 0; i < 8; i++) {
            const int lin = i * 512 + tid;        // 0..4095
            const int p = lin >> 8, c = lin & 255;
            Wp[p][c] = pack2(__ldg(&Woff[p * Cn + c]), __ldg(&Woff[(p + 16) * Cn + c]));
        }
    }
    __syncthreads();

    // ---- Phase 2: offset GEMM ----
    // lane = 4*(posl%4-part) mapping: cq = lane&7, pl = lane>>3; posl = warp*4 + pl
    {
        const int lane = tid & 31;
        const int cq   = lane & 7;
        const int posl = (tid >> 5) * 4 + (lane >> 3);

        ull acc[16];
        #pragma unroll
        for (int p = 0; p < 16; p++) acc[p] = 0ull;

        const int c0 = cq * 32;
        #pragma unroll 4
        for (int cc = 0; cc < 32; cc += 2) {
            const int c = c0 + cc;
            const float xv0 = xs[c][posl];
            const float xv1 = xs[c + 1][posl];
            const ull xp0 = pack2(xv0, xv0);
            const ull xp1 = pack2(xv1, xv1);
            #pragma unroll
            for (int p = 0; p < 16; p++) {
                ulonglong2 wv = *(const ulonglong2*)&Wp[p][c];
                ffma2(acc[p], wv.x, xp0);
                ffma2(acc[p], wv.y, xp1);
            }
        }
        __syncthreads();   // all Wp reads done before sxy overlay writes

        // shfl.bfly reduction over cq bits; thread ends with packs 2cq, 2cq+1
        #pragma unroll
        for (int m = 4; m >= 1; m >>= 1) {
            const int half = 2 * m;
            const bool up = (cq & m);
            #pragma unroll
            for (int i = 0; i < 8; i++) {
                if (i < half) {
                    const ull lo_ = acc[i];
                    const ull hi_ = acc[i + half];
                    const ull send = up ? lo_ : hi_;
                    const ull recv = __shfl_xor_sync(0xffffffffu, send, m);
                    acc[i] = up ? add2(hi_, recv) : add2(lo_, recv);
                }
            }
        }

        #pragma unroll
        for (int t = 0; t < 2; t++) {
            const int p = 2 * cq + t;
            float lo, hi;
            unpack2(acc[t], lo, hi);
            const float ipx = (p & 1) ? 0.25f : -0.25f;
            const float ipy = ((p >> 1) & 1) ? 0.25f : -0.25f;
            sxy[0][p][posl] = (float)posl + 0.25f * (lo + __ldg(boff + p)) + ipx;
            sxy[1][p][posl] = (float)h    + 0.25f * (hi + __ldg(boff + p + 16)) + ipy;
        }
    }
    __syncthreads();

    // ---- Phase 3: 3x3-neighborhood gather ----
    // warp: wh = warp&1 (wq half), slab = warp>>1 (32 channels); lane = wq offset
    {
        const int warp = tid >> 5, lane = tid & 31;
        const int wh   = warp & 1;
        const int wq   = wh * 32 + lane;
        const int slab = warp >> 1;               // 0..7
        const int cloc = slab * 32;               // local channel base
        const int g    = slab >> 1;

        // packed separable coefficients over the (rx0, rx1) pair
        ull xcp[2][3], ycp[2][3];
        #pragma unroll
        for (int ry = 0; ry < 2; ry++) {
            float xc[2][3], yc[2][3];
            #pragma unroll
            for (int rx = 0; rx < 2; rx++) {
                const int j = g * 4 + ry * 2 + rx;
                const float ix = sxy[0][j][wq];
                const float iy = sxy[1][j][wq];
                const float xf = floorf(ix);
                const float yf = floorf(iy);
                const float wx = ix - xf;
                const float wy = iy - yf;
                const bool xh = (xf >= (float)wq);
                const bool yh = (yf >= (float)h);
                xc[rx][0] = xh ? 0.f : 1.f - wx;
                xc[rx][1] = xh ? 1.f - wx : wx;
                xc[rx][2] = xh ? wx : 0.f;
                yc[rx][0] = yh ? 0.f : 1.f - wy;
                yc[rx][1] = yh ? 1.f - wy : wy;
                yc[rx][2] = yh ? wy : 0.f;
            }
            #pragma unroll
            for (int i = 0; i < 3; i++) {
                xcp[ry][i] = pack2(xc[0][i], xc[1][i]);
                ycp[ry][i] = pack2(yc[0][i], yc[1][i]);
            }
        }
        const int xl = max(wq - 1, 0);
        const int xm = wq;
        const int xr = min(wq + 1, Wn - 1);
        const int ym = max(h - 1, 0);
        const int yp = min(h + 1, Hn - 1);
        const int oy0 = 2 * h;
        const int ox0 = 2 * wq;

        const float* xb = x + (((size_t)b * Cn + cloc) * Hn) * Wn;
        float* ob = out + (((size_t)(b * Cn + cloc) * OH + oy0) * OW + ox0);

        #pragma unroll 4
        for (int k = 0; k < 32; k++) {
            const int c = cloc + k;
            const float* rowm = xb + (size_t)k * NPOS + (size_t)ym * Wn;
            const float* rowp = xb + (size_t)k * NPOS + (size_t)yp * Wn;
            // batch the 6 gmem loads (independent -> MLP)
            const float ml = __ldg(rowm + xl);
            const float mm = __ldg(rowm + xm);
            const float mr = __ldg(rowm + xr);
            const float pl = __ldg(rowp + xl);
            const float pm = __ldg(rowp + xm);
            const float pr = __ldg(rowp + xr);
            const float hl = xs[c][xl];
            const float hm = xs[c][xm];
            const float hr = xs[c][xr];

            ull vp[9];
            vp[0] = pack2(ml, ml); vp[1] = pack2(mm, mm); vp[2] = pack2(mr, mr);
            vp[3] = pack2(hl, hl); vp[4] = pack2(hm, hm); vp[5] = pack2(hr, hr);
            vp[6] = pack2(pl, pl); vp[7] = pack2(pm, pm); vp[8] = pack2(pr, pr);

            float* op = ob + (size_t)k * (OH * OW);
            #pragma unroll
            for (int ry = 0; ry < 2; ry++) {
                ull t0 = mul2(xcp[ry][0], vp[0]);
                ffma2(t0, xcp[ry][1], vp[1]);
                ffma2(t0, xcp[ry][2], vp[2]);
                ull t1 = mul2(xcp[ry][0], vp[3]);
                ffma2(t1, xcp[ry][1], vp[4]);
                ffma2(t1, xcp[ry][2], vp[5]);
                ull t2 = mul2(xcp[ry][0], vp[6]);
                ffma2(t2, xcp[ry][1], vp[7]);
                ffma2(t2, xcp[ry][2], vp[8]);
                ull a = mul2(ycp[ry][0], t0);
                ffma2(a, ycp[ry][1], t1);
                ffma2(a, ycp[ry][2], t2);
                *(ull*)(op + (size_t)ry * OW) = a;   // (lo,hi) = (rx0, rx1)
            }
        }
    }
}

extern "C" void kernel_launch(void* const* d_in, const int* in_sizes, int n_in,
                              void* d_out, int out_size) {
    const float* x    = (const float*)d_in[0];
    const float* Woff = (const float*)d_in[1];
    const float* boff = (const float*)d_in[2];
    float* out = (float*)d_out;

    cudaFuncSetAttribute(dysample_fused,
                         cudaFuncAttributeMaxDynamicSharedMemorySize, SMEM_TOTAL);

    dim3 grid(Hn, Bn);
    dysample_fused<<<grid, 512, SMEM_TOTAL>>>(x, Woff, boff, out);
}

// round 14
// speedup vs baseline: 4.4698x; 4.4698x over previous
#include <cuda_runtime.h>
#include <cuda_bf16.h>
#include <cstdint>

// DySample fused single-kernel: x(8,256,64,64), W_off(32,256), b_off(32)
//   -> out(8,256,128,128), fp32.
// Block = (h, b), 512 threads, 104KB smem:
//   Phase 1: stage x[b,:,h,:] (64KB) + packed W (32KB).
//   Phase 2: offset GEMM, posl=tid&63 (stride-1 xs reads), cq=tid>>6
//            (warp-uniform -> Wp broadcast). Two-stage smem reduction in a
//            32KB overlay (red[16][4][64]), coords -> separate sxy (8KB).
//   Phase 3: 3x3-neighborhood gather (row h from smem, rows h+-1 via __ldg/L2),
//            packed-separable f32x2 weights, b64 stores.
// ix = w + (0.25*off_x + ipx), iy = h + (0.25*off_y + ipy);
// j = g*4+ry*2+rx; o_x=j, o_y=16+j; ipx=(j&1)?+.25:-.25, ipy=((j>>1)&1)?+.25:-.25

#define Bn 8
#define Cn 256
#define Hn 64
#define Wn 64
#define NPOS 4096
#define OH 128
#define OW 128

#define SMEM_XS    0                    // float xs[256][64]        = 65536 B
#define SMEM_WP    65536                // ull Wp[16][256] = 32KB; red[16][4][64] f2 = 32KB
#define SMEM_SXY   (65536 + 32768)      // float sxy[2][16][64]     =  8192 B
#define SMEM_TOTAL (65536 + 32768 + 8192)

typedef unsigned long long ull;

__device__ __forceinline__ void ffma2(ull &d, ull a, ull b) {
    asm("fma.rn.f32x2 %0, %1, %2, %0;" : "+l"(d) : "l"(a), "l"(b));
}
__device__ __forceinline__ ull mul2(ull a, ull b) {
    ull r;
    asm("mul.rn.f32x2 %0, %1, %2;" : "=l"(r) : "l"(a), "l"(b));
    return r;
}
__device__ __forceinline__ ull pack2(float lo, float hi) {
    ull r;
    asm("mov.b64 %0, {%1, %2};" : "=l"(r) : "f"(lo), "f"(hi));
    return r;
}
__device__ __forceinline__ void unpack2(ull v, float &lo, float &hi) {
    asm("mov.b64 {%0, %1}, %2;" : "=f"(lo), "=f"(hi) : "l"(v));
}

__global__ __launch_bounds__(512, 2) void dysample_fused(
    const float* __restrict__ x,
    const float* __restrict__ Woff,
    const float* __restrict__ boff,
    float* __restrict__ out)
{
    extern __shared__ __align__(16) char dsm[];
    float (*xs)[64]      = reinterpret_cast<float(*)[64]>(dsm + SMEM_XS);
    ull   (*Wp)[256]     = reinterpret_cast<ull(*)[256]>(dsm + SMEM_WP);
    float2 (*red)[4][64] = reinterpret_cast<float2(*)[4][64]>(dsm + SMEM_WP); // 32KB exactly
    float (*sxy)[16][64] = reinterpret_cast<float(*)[16][64]>(dsm + SMEM_SXY);

    const int tid = threadIdx.x;
    const int h   = blockIdx.x;
    const int b   = blockIdx.y;

    // ---- Phase 1: stage x row-slab + packed W ----
    #pragma unroll
    for (int i = 0; i < 8; i++) {
        const int lin = i * 512 + tid;            // 0..4095
        const int c  = lin >> 4;
        const int w4 = lin & 15;
        const float4 v = __ldg((const float4*)(x
            + (((size_t)b * Cn + c) * Hn + h) * Wn) + w4);
        *(float4*)&xs[c][w4 * 4] = v;
    }
    #pragma unroll
    for (int i = 0; i < 8; i++) {
        const int lin = i * 512 + tid;            // 0..4095
        const int p = lin >> 8, c = lin & 255;
        Wp[p][c] = pack2(__ldg(&Woff[p * Cn + c]), __ldg(&Woff[(p + 16) * Cn + c]));
    }
    __syncthreads();

    // ---- Phase 2: offset GEMM (R6 access pattern, x from smem) ----
    {
        const int posl = tid & 63;                // lane-contiguous -> stride-1 xs
        const int cq   = tid >> 6;                // 0..7, warp-uniform -> Wp broadcast

        ull acc[16];
        #pragma unroll
        for (int p = 0; p < 16; p++) acc[p] = 0ull;

        const int c0 = cq * 32;
        #pragma unroll 4
        for (int cc = 0; cc < 32; cc += 2) {
            const int c = c0 + cc;
            const float xv0 = xs[c][posl];
            const float xv1 = xs[c + 1][posl];
            const ull xp0 = pack2(xv0, xv0);
            const ull xp1 = pack2(xv1, xv1);
            #pragma unroll
            for (int p = 0; p < 16; p++) {
                ulonglong2 wv = *(const ulonglong2*)&Wp[p][c];
                ffma2(acc[p], wv.x, xp0);
                ffma2(acc[p], wv.y, xp1);
            }
        }
        __syncthreads();                          // Wp dead; red overlay (32KB)

        // stage 1: cq 4..7 deposit partials
        if (cq >= 4) {
            #pragma unroll
            for (int p = 0; p < 16; p++) {
                float lo, hi;
                unpack2(acc[p], lo, hi);
                red[p][cq - 4][posl] = make_float2(lo, hi);
            }
        }
        __syncthreads();
        // stage 2: cq 0..3 add their own and write back
        if (cq < 4) {
            #pragma unroll
            for (int p = 0; p < 16; p++) {
                float lo, hi;
                unpack2(acc[p], lo, hi);
                float2 u = red[p][cq][posl];
                u.x += lo; u.y += hi;
                red[p][cq][posl] = u;
            }
        }
        __syncthreads();

        // final reduce: 1024 (p, posl) entries, 2 per thread, 4-way sum
        #pragma unroll
        for (int e = tid; e < 1024; e += 512) {
            const int p  = e >> 6;
            const int pl = e & 63;
            float2 s = red[p][0][pl];
            #pragma unroll
            for (int q = 1; q < 4; q++) {
                const float2 u = red[p][q][pl];
                s.x += u.x; s.y += u.y;
            }
            const float ipx = (p & 1) ? 0.25f : -0.25f;
            const float ipy = ((p >> 1) & 1) ? 0.25f : -0.25f;
            sxy[0][p][pl] = (float)pl + 0.25f * (s.x + __ldg(boff + p)) + ipx;
            sxy[1][p][pl] = (float)h  + 0.25f * (s.y + __ldg(boff + p + 16)) + ipy;
        }
    }
    __syncthreads();

    // ---- Phase 3: 3x3-neighborhood gather ----
    {
        const int warp = tid >> 5, lane = tid & 31;
        const int wh   = warp & 1;
        const int wq   = wh * 32 + lane;
        const int slab = warp >> 1;               // 0..7 -> 32 channels each
        const int cloc = slab * 32;
        const int g    = slab >> 1;

        ull xcp[2][3], ycp[2][3];
        #pragma unroll
        for (int ry = 0; ry < 2; ry++) {
            float xc[2][3], yc[2][3];
            #pragma unroll
            for (int rx = 0; rx < 2; rx++) {
                const int j = g * 4 + ry * 2 + rx;
                const float ix = sxy[0][j][wq];
                const float iy = sxy[1][j][wq];
                const float xf = floorf(ix);
                const float yf = floorf(iy);
                const float wx = ix - xf;
                const float wy = iy - yf;
                const bool xh = (xf >= (float)wq);
                const bool yh = (yf >= (float)h);
                xc[rx][0] = xh ? 0.f : 1.f - wx;
                xc[rx][1] = xh ? 1.f - wx : wx;
                xc[rx][2] = xh ? wx : 0.f;
                yc[rx][0] = yh ? 0.f : 1.f - wy;
                yc[rx][1] = yh ? 1.f - wy : wy;
                yc[rx][2] = yh ? wy : 0.f;
            }
            #pragma unroll
            for (int i = 0; i < 3; i++) {
                xcp[ry][i] = pack2(xc[0][i], xc[1][i]);
                ycp[ry][i] = pack2(yc[0][i], yc[1][i]);
            }
        }
        const int xl = max(wq - 1, 0);
        const int xm = wq;
        const int xr = min(wq + 1, Wn - 1);
        const int ym = max(h - 1, 0);
        const int yp = min(h + 1, Hn - 1);
        const int oy0 = 2 * h;
        const int ox0 = 2 * wq;

        const float* xb = x + (((size_t)b * Cn + cloc) * Hn) * Wn;
        float* ob = out + (((size_t)(b * Cn + cloc) * OH + oy0) * OW + ox0);

        #pragma unroll 4
        for (int k = 0; k < 32; k++) {
            const int c = cloc + k;
            const float* rowm = xb + (size_t)k * NPOS + (size_t)ym * Wn;
            const float* rowp = xb + (size_t)k * NPOS + (size_t)yp * Wn;
            const float ml = __ldg(rowm + xl);
            const float mm = __ldg(rowm + xm);
            const float mr = __ldg(rowm + xr);
            const float pl = __ldg(rowp + xl);
            const float pm = __ldg(rowp + xm);
            const float pr = __ldg(rowp + xr);
            const float hl = xs[c][xl];
            const float hm = xs[c][xm];
            const float hr = xs[c][xr];

            ull vp[9];
            vp[0] = pack2(ml, ml); vp[1] = pack2(mm, mm); vp[2] = pack2(mr, mr);
            vp[3] = pack2(hl, hl); vp[4] = pack2(hm, hm); vp[5] = pack2(hr, hr);
            vp[6] = pack2(pl, pl); vp[7] = pack2(pm, pm); vp[8] = pack2(pr, pr);

            float* op = ob + (size_t)k * (OH * OW);
            #pragma unroll
            for (int ry = 0; ry < 2; ry++) {
                ull t0 = mul2(xcp[ry][0], vp[0]);
                ffma2(t0, xcp[ry][1], vp[1]);
                ffma2(t0, xcp[ry][2], vp[2]);
                ull t1 = mul2(xcp[ry][0], vp[3]);
                ffma2(t1, xcp[ry][1], vp[4]);
                ffma2(t1, xcp[ry][2], vp[5]);
                ull t2 = mul2(xcp[ry][0], vp[6]);
                ffma2(t2, xcp[ry][1], vp[7]);
                ffma2(t2, xcp[ry][2], vp[8]);
                ull a = mul2(ycp[ry][0], t0);
                ffma2(a, ycp[ry][1], t1);
                ffma2(a, ycp[ry][2], t2);
                *(ull*)(op + (size_t)ry * OW) = a;   // (lo,hi) = (rx0, rx1)
            }
        }
    }
}

extern "C" void kernel_launch(void* const* d_in, const int* in_sizes, int n_in,
                              void* d_out, int out_size) {
    const float* x    = (const float*)d_in[0];
    const float* Woff = (const float*)d_in[1];
    const float* boff = (const float*)d_in[2];
    float* out = (float*)d_out;

    cudaFuncSetAttribute(dysample_fused,
                         cudaFuncAttributeMaxDynamicSharedMemorySize, SMEM_TOTAL);

    dim3 grid(Hn, Bn);
    dysample_fused<<<grid, 512, SMEM_TOTAL>>>(x, Woff, boff, out);
}

// round 15
// speedup vs baseline: 5.0645x; 1.1331x over previous
#include <cuda_runtime.h>
#include <cuda_bf16.h>
#include <cstdint>

// DySample: x(8,256,64,64), W_off(32,256), b_off(32) -> out(8,256,128,128), fp32.
//   A (R6 config, measured best): offsets -> final sample coords -> 4MB scratch.
//   B: h-pair 3x3-neighborhood gather: stage 4 rows for 2 output row-pairs
//      (amortizes row staging 3x->2x), packed-separable f32x2 weights, b64 stores.
// ix = w + (0.25*off_x + ipx), iy = h + (0.25*off_y + ipy);
// j = g*4+ry*2+rx; o_x=j, o_y=16+j; ipx=(j&1)?+.25:-.25, ipy=((j>>1)&1)?+.25:-.25

#define Bn 8
#define Cn 256
#define Hn 64
#define Wn 64
#define NPOS 4096
#define OH 128
#define OW 128

typedef unsigned long long ull;

__device__ float d_coord[Bn * 32 * NPOS];   // 4 MB scratch

__device__ __forceinline__ void ffma2(ull &d, ull a, ull b) {
    asm("fma.rn.f32x2 %0, %1, %2, %0;" : "+l"(d) : "l"(a), "l"(b));
}
__device__ __forceinline__ ull mul2(ull a, ull b) {
    ull r;
    asm("mul.rn.f32x2 %0, %1, %2;" : "=l"(r) : "l"(a), "l"(b));
    return r;
}
__device__ __forceinline__ ull pack2(float lo, float hi) {
    ull r;
    asm("mov.b64 %0, {%1, %2};" : "=l"(r) : "f"(lo), "f"(hi));
    return r;
}
__device__ __forceinline__ void unpack2(ull v, float &lo, float &hi) {
    asm("mov.b64 {%0, %1}, %2;" : "=f"(lo), "=f"(hi) : "l"(v));
}

// ---------------- Kernel A: offset GEMM (R6 config, unchanged) ----------------
__global__ __launch_bounds__(256) void offset_kernel(
    const float* __restrict__ x,
    const float* __restrict__ Woff,
    const float* __restrict__ boff)
{
    __shared__ __align__(16) char sraw[32768];
    ull (*Wp)[256] = reinterpret_cast<ull(*)[256]>(sraw);            // [16][256] 32KB
    float2 (*red)[8][32] = reinterpret_cast<float2(*)[8][32]>(sraw); // [16][8][32] 32KB

    const int tid  = threadIdx.x;
    const int b    = blockIdx.y;
    const int posl = tid & 31;
    const int cq   = tid >> 5;                 // 0..7 (warp-uniform)
    const int gpos = blockIdx.x * 32 + posl;

    #pragma unroll
    for (int i = 0; i < 16; i++) {
        const int idx = i * 256 + tid;
        const int p = idx >> 8, c = idx & 255;
        Wp[p][c] = pack2(Woff[p * Cn + c], Woff[(p + 16) * Cn + c]);
    }
    __syncthreads();

    ull acc[16];
    #pragma unroll
    for (int p = 0; p < 16; p++) acc[p] = 0ull;

    const float* xb = x + (size_t)b * Cn * NPOS + gpos;
    const int c0 = cq * 32;

    #pragma unroll 4
    for (int cc = 0; cc < 32; cc += 2) {
        const int c = c0 + cc;
        const float xv0 = __ldg(xb + (size_t)c * NPOS);
        const float xv1 = __ldg(xb + (size_t)(c + 1) * NPOS);
        const ull xp0 = pack2(xv0, xv0);
        const ull xp1 = pack2(xv1, xv1);
        #pragma unroll
        for (int p = 0; p < 16; p++) {
            ulonglong2 wv = *(const ulonglong2*)&Wp[p][c];
            ffma2(acc[p], wv.x, xp0);
            ffma2(acc[p], wv.y, xp1);
        }
    }
    __syncthreads();

    #pragma unroll
    for (int p = 0; p < 16; p++) {
        float lo, hi;
        unpack2(acc[p], lo, hi);
        red[p][cq][posl] = make_float2(lo, hi);
    }
    __syncthreads();

    const int pp = tid >> 5;
    const int w = gpos & 63;
    const int h = gpos >> 6;
    #pragma unroll
    for (int t = 0; t < 2; t++) {
        const int p = pp * 2 + t;
        float2 s = red[p][0][posl];
        #pragma unroll
        for (int q = 1; q < 8; q++) {
            float2 u = red[p][q][posl];
            s.x += u.x; s.y += u.y;
        }
        const float ipx = (p & 1) ? 0.25f : -0.25f;
        const float ipy = ((p >> 1) & 1) ? 0.25f : -0.25f;
        const float cx = (float)w + 0.25f * (s.x + __ldg(boff + p)) + ipx;
        const float cy = (float)h + 0.25f * (s.y + __ldg(boff + p + 16)) + ipy;
        d_coord[(size_t)(b * 32 + p) * NPOS + gpos]      = cx;
        d_coord[(size_t)(b * 32 + p + 16) * NPOS + gpos] = cy;
    }
}

// ---------------- Kernel B: h-pair 3x3 gather, packed-separable weights ------
// grid (32, 8, 8) = (h-pair, b, g*2+half32). 256 threads.
// Stage rows 2hp-1 .. 2hp+2 (clamped) x 32 channels; output rows 4hp..4hp+3.
__global__ __launch_bounds__(256) void gather_kernel(
    const float* __restrict__ x,
    float* __restrict__ out)
{
    __shared__ float xs[4][32][64];       // 32 KB, [row][c][w]
    __shared__ float sxy[2][2][4][64];    // 8 KB, [hh][xy][jj][w]

    const int tid  = threadIdx.x;
    const int hp   = blockIdx.x;          // 0..31 -> h in {2hp, 2hp+1}
    const int b    = blockIdx.y;
    const int g    = blockIdx.z >> 1;
    const int half = blockIdx.z & 1;
    const int cstage = b * Cn + g * 64 + half * 32;

    // stage coords for both h's of the pair, this group's 4 j's
    #pragma unroll
    for (int i = 0; i < 4; i++) {
        const int lin = i * 256 + tid;            // 0..1023
        const int w  = lin & 63;
        const int jj = (lin >> 6) & 3;
        const int xy = (lin >> 8) & 1;
        const int hh = lin >> 9;
        sxy[hh][xy][jj][w] =
            d_coord[(size_t)(b * 32 + xy * 16 + g * 4 + jj) * NPOS
                    + ((hp * 2 + hh) << 6) + w];
    }

    // stage 4 input rows (clamped) x 32 channels, float4 coalesced
    #pragma unroll
    for (int i = 0; i < 8; i++) {
        const int lin = i * 256 + tid;            // 0..2047
        const int w4 = lin & 15;
        const int rr = (lin >> 4) & 3;
        const int c  = lin >> 6;                  // 0..31
        const int rowy = min(max(hp * 2 - 1 + rr, 0), Hn - 1);
        const float4 v = __ldg((const float4*)(x
            + (((size_t)(cstage + c)) * Hn + rowy) * Wn) + w4);
        *(float4*)&xs[rr][c][w4 * 4] = v;
    }
    __syncthreads();

    const int warp = tid >> 5, lane = tid & 31;
    const int wh    = warp & 1;
    const int wq    = wh * 32 + lane;
    const int kbase = (warp >> 1) * 8;            // 8 channels per warp
    const int xl = max(wq - 1, 0);
    const int xm = wq;
    const int xr = min(wq + 1, Wn - 1);
    const int ox0 = 2 * wq;

    #pragma unroll
    for (int hh = 0; hh < 2; hh++) {
        const int h = hp * 2 + hh;

        // packed separable coefficients over the (rx0, rx1) pair
        ull xcp[2][3], ycp[2][3];
        #pragma unroll
        for (int ry = 0; ry < 2; ry++) {
            float xc[2][3], yc[2][3];
            #pragma unroll
            for (int rx = 0; rx < 2; rx++) {
                const int j = ry * 2 + rx;
                const float ix = sxy[hh][0][j][wq];
                const float iy = sxy[hh][1][j][wq];
                const float xf = floorf(ix);
                const float yf = floorf(iy);
                const float wx = ix - xf;
                const float wy = iy - yf;
                const bool xh2 = (xf >= (float)wq);
                const bool yh2 = (yf >= (float)h);
                xc[rx][0] = xh2 ? 0.f : 1.f - wx;
                xc[rx][1] = xh2 ? 1.f - wx : wx;
                xc[rx][2] = xh2 ? wx : 0.f;
                yc[rx][0] = yh2 ? 0.f : 1.f - wy;
                yc[rx][1] = yh2 ? 1.f - wy : wy;
                yc[rx][2] = yh2 ? wy : 0.f;
            }
            #pragma unroll
            for (int i = 0; i < 3; i++) {
                xcp[ry][i] = pack2(xc[0][i], xc[1][i]);
                ycp[ry][i] = pack2(yc[0][i], yc[1][i]);
            }
        }

        const int oy0 = 2 * h;
        // rows for output h: staged indices hh, hh+1, hh+2
        #pragma unroll
        for (int kk = 0; kk < 8; kk++) {
            const int k = kbase + kk;
            ull vp[9];
            #pragma unroll
            for (int r = 0; r < 3; r++) {
                const float vL = xs[hh + r][k][xl];
                const float vM = xs[hh + r][k][xm];
                const float vR = xs[hh + r][k][xr];
                vp[r * 3 + 0] = pack2(vL, vL);
                vp[r * 3 + 1] = pack2(vM, vM);
                vp[r * 3 + 2] = pack2(vR, vR);
            }
            float* op = out + (((size_t)(cstage + k) * OH + oy0) * OW + ox0);
            #pragma unroll
            for (int ry = 0; ry < 2; ry++) {
                ull t0 = mul2(xcp[ry][0], vp[0]);
                ffma2(t0, xcp[ry][1], vp[1]);
                ffma2(t0, xcp[ry][2], vp[2]);
                ull t1 = mul2(xcp[ry][0], vp[3]);
                ffma2(t1, xcp[ry][1], vp[4]);
                ffma2(t1, xcp[ry][2], vp[5]);
                ull t2 = mul2(xcp[ry][0], vp[6]);
                ffma2(t2, xcp[ry][1], vp[7]);
                ffma2(t2, xcp[ry][2], vp[8]);
                ull a = mul2(ycp[ry][0], t0);
                ffma2(a, ycp[ry][1], t1);
                ffma2(a, ycp[ry][2], t2);
                *(ull*)(op + (size_t)ry * OW) = a;   // (lo,hi) = (rx0, rx1)
            }
        }
    }
}

extern "C" void kernel_launch(void* const* d_in, const int* in_sizes, int n_in,
                              void* d_out, int out_size) {
    const float* x    = (const float*)d_in[0];
    const float* Woff = (const float*)d_in[1];
    const float* boff = (const float*)d_in[2];
    float* out = (float*)d_out;

    dim3 gridA(128, Bn);
    offset_kernel<<<gridA, 256>>>(x, Woff, boff);

    dim3 gridB(32, Bn, 8);
    gather_kernel<<<gridB, 256>>>(x, out);
}